// round 1
// baseline (speedup 1.0000x reference)
#include <cuda_runtime.h>
#include <cstdint>

typedef unsigned long long u64;

#define N_ENT      50000
#define N_EDGES    800000
#define D_PE       16

// Device scratch (no allocs allowed): bitmask BFS state, 8B per entity each.
__device__ u64 g_frontier[N_ENT];
__device__ u64 g_next[N_ENT];
__device__ u64 g_visited[N_ENT];
__device__ u64 g_cnt[N_ENT];      // packed byte counts: c0 | c1<<8 | c2<<16 | c3<<24
__device__ int g_nvalid;

// ---------------------------------------------------------------------------
// Zero all state (must run every replay: graph is re-executed many times).
__global__ void k_init() {
    int n = blockIdx.x * blockDim.x + threadIdx.x;
    if (n < N_ENT) {
        g_frontier[n] = 0ull;
        g_next[n]     = 0ull;
        g_visited[n]  = 0ull;
        g_cnt[n]      = 0ull;
    }
}

// ---------------------------------------------------------------------------
// Gather 64 anchor entities, mark unique ones (bit index = original slot —
// bits need not be contiguous, only distinct), seed frontier/visited/cnt.
__global__ void k_setup(const int* __restrict__ h,
                        const int* __restrict__ t,
                        const int* __restrict__ aidx) {
    __shared__ int vals[64];
    __shared__ int cnt;
    int i = threadIdx.x;          // 64 threads
    if (i == 0) cnt = 0;
    int e = aidx[i < 32 ? i : i - 32];
    vals[i] = (i < 32) ? h[e] : t[e];
    __syncthreads();
    int v = vals[i];
    bool uniq = true;
    for (int j = 0; j < i; j++)
        if (vals[j] == v) uniq = false;
    if (uniq) {
        u64 bit = 1ull << i;
        atomicOr(&g_frontier[v], bit);
        atomicOr(&g_visited[v], bit);
        atomicAdd(&g_cnt[v], 1ull);   // depth-0 count (low byte)
        atomicAdd(&cnt, 1);
    }
    __syncthreads();
    if (i == 0) g_nvalid = cnt;
}

// ---------------------------------------------------------------------------
// Push one BFS round along both edge directions. Predicates skip atomics when
// the source frontier is empty or the destination already has all those bits.
__global__ void k_prop(const int* __restrict__ h, const int* __restrict__ t) {
    int i = blockIdx.x * blockDim.x + threadIdx.x;
    if (i >= N_EDGES) return;
    int s = __ldg(h + i);
    int d = __ldg(t + i);
    u64 fs = g_frontier[s];
    u64 fd = g_frontier[d];
    if (fs) {
        u64 vd = g_visited[d];
        if (fs & ~vd) atomicOr(&g_next[d], fs);
    }
    if (fd) {
        u64 vs = g_visited[s];
        if (fd & ~vs) atomicOr(&g_next[s], fd);
    }
}

// ---------------------------------------------------------------------------
// Fold next into visited, record popcount of newly-reached bits at this depth,
// advance frontier. shift = 8*depth (depth = 1..3 stored; depth 4 is fused
// into the final kernel; depth 5 provably changes nothing).
__global__ void k_update(int shift) {
    int n = blockIdx.x * blockDim.x + threadIdx.x;
    if (n >= N_ENT) return;
    u64 nf = g_next[n];
    g_next[n] = 0ull;
    u64 vis   = g_visited[n];
    u64 newly = nf & ~vis;
    g_frontier[n] = newly;
    if (newly) {
        g_visited[n] = vis | newly;
        g_cnt[n] += (u64)__popcll(newly) << shift;
    }
}

// ---------------------------------------------------------------------------
// Depth-4 newly-count + embedding combine + output, fused.
// out[n][j] = (1/nv) * ( sum_{d=0..4} c_d * E[d][j] + (nv - sum c_d) * E[5][j] )
__global__ void k_final(const float* __restrict__ embed,
                        float* __restrict__ out) {
    __shared__ float E[6 * D_PE];
    int tid = threadIdx.x;
    if (tid < 6 * D_PE) E[tid] = embed[tid];
    __syncthreads();
    int n = blockIdx.x * blockDim.x + tid;
    if (n >= N_ENT) return;

    u64 nf    = g_next[n];
    u64 vis   = g_visited[n];
    int c4    = __popcll(nf & ~vis);
    u64 c     = g_cnt[n];
    int c0 =  (int)(c        & 0xFF);
    int c1 =  (int)((c >> 8) & 0xFF);
    int c2 =  (int)((c >> 16)& 0xFF);
    int c3 =  (int)((c >> 24)& 0xFF);
    int nv = g_nvalid;
    int rem = nv - (c0 + c1 + c2 + c3 + c4);
    float inv = 1.0f / (float)nv;
    float w0 = c0 * inv, w1 = c1 * inv, w2 = c2 * inv;
    float w3 = c3 * inv, w4 = c4 * inv, w5 = rem * inv;

    float* o = out + (size_t)n * D_PE;
#pragma unroll
    for (int j = 0; j < D_PE; j++) {
        o[j] = w0 * E[j]
             + w1 * E[D_PE     + j]
             + w2 * E[2*D_PE   + j]
             + w3 * E[3*D_PE   + j]
             + w4 * E[4*D_PE   + j]
             + w5 * E[5*D_PE   + j];
    }
}

// ---------------------------------------------------------------------------
extern "C" void kernel_launch(void* const* d_in, const int* in_sizes, int n_in,
                              void* d_out, int out_size) {
    const int*   h     = (const int*)d_in[0];   // [800000]
    const int*   t     = (const int*)d_in[1];   // [800000]
    const int*   aidx  = (const int*)d_in[2];   // [32]
    // d_in[3] = num_entities (scalar, compile-time constant here)
    const float* embed = (const float*)d_in[4]; // [6,16]
    float*       out   = (float*)d_out;         // [50000,16]

    const int TB = 256;
    const int GN = (N_ENT   + TB - 1) / TB;     // 196
    const int GE = (N_EDGES + TB - 1) / TB;     // 3125

    k_init <<<GN, TB>>>();
    k_setup<<<1, 64>>>(h, t, aidx);

    // depths 1..3: propagate + update
    for (int depth = 1; depth <= 3; ++depth) {
        k_prop  <<<GE, TB>>>(h, t);
        k_update<<<GN, TB>>>(8 * depth);
    }
    // depth 4 propagate, then fused depth-4 count + output
    k_prop <<<GE, TB>>>(h, t);
    k_final<<<GN, TB>>>(embed, out);
}